// round 11
// baseline (speedup 1.0000x reference)
#include <cuda_runtime.h>
#include <cuda_fp16.h>
#include <mma.h>
#include <math.h>
#include <stdint.h>

using namespace nvcuda;

// Linear attention, wmma m16n16k16 + 3xFP16 hi/lo splitting.
// R11: all operands kept in wmma-native orientation (row/col major fragments),
// so every smem fill is a contiguous cp.async copy; 2-stage pipeline;
// __launch_bounds__(256,2) for 2 CTAs/SM.
//   conv:  xh/xl = split(x);  wh/wl = split(256*W)
//   proj:  acc = x @ 256W;  qh/ql = split(exp(acc/256)/16) = split(16*q'')
//   zc  :  zc[l] = 4096 / (16*sum(qh+ql) + 1e-8)
//   kv  :  acc = (16k'')^T @ x = kv/16;  kvh/kvl = split(acc/16) = split(kv/256)
//   num :  acc = (16q'') @ (kv/256) = q'*kv/4096;  out = acc * zc[l]

#define BATCH 8
#define LSEQ  4096
#define DDIM  1024
#define EDIM  256
#define BL    (BATCH * LSEQ)
#define SPA   24    // row-major A tile pitch (16 data + 8 pad halves)
#define SPB   136   // [16 k][128 mn] tile pitch

// ---- scratch ----
__device__ __align__(16) __half g_xh[(size_t)BL * DDIM];   // [l][d]
__device__ __align__(16) __half g_xl[(size_t)BL * DDIM];
__device__ __align__(16) __half g_wqh[DDIM * EDIM];        // [d][e], 256W
__device__ __align__(16) __half g_wql[DDIM * EDIM];
__device__ __align__(16) __half g_wkh[DDIM * EDIM];
__device__ __align__(16) __half g_wkl[DDIM * EDIM];
__device__ __align__(16) __half g_qh[(size_t)BL * EDIM];   // [l][e], 16q''
__device__ __align__(16) __half g_ql[(size_t)BL * EDIM];
__device__ __align__(16) __half g_kh[(size_t)BL * EDIM];
__device__ __align__(16) __half g_kl[(size_t)BL * EDIM];
__device__ __align__(16) __half g_kvh[(size_t)BATCH * EDIM * DDIM];  // [b][e][d]
__device__ __align__(16) __half g_kvl[(size_t)BATCH * EDIM * DDIM];
__device__ float g_zc[BL];

// ---------------- helpers ----------------
__device__ __forceinline__ void split2(float x, __half& h, __half& l) {
    h = __float2half_rn(x);
    l = __float2half_rn(x - __half2float(h));
}
__device__ __forceinline__ uint32_t sptr(const void* p) {
    return (uint32_t)__cvta_generic_to_shared(p);
}
#define CP16(dst, src) \
    asm volatile("cp.async.cg.shared.global [%0], [%1], 16;" :: "r"(dst), "l"(src))
#define CP_COMMIT() asm volatile("cp.async.commit_group;")
#define CP_WAIT1()  asm volatile("cp.async.wait_group 1;")
#define CP_WAIT0()  asm volatile("cp.async.wait_group 0;")

// A row-major ([m][k] tile, pitch SPA), B row-major ([k][n] tile, pitch SPB)
__device__ __forceinline__ void mma_rowA(
    const __half* Ah, const __half* Al, const __half* Bh, const __half* Bl,
    wmma::fragment<wmma::accumulator, 16, 16, 16, float> acc[4][2],
    int warpM, int warpN)
{
    wmma::fragment<wmma::matrix_b, 16, 16, 16, __half, wmma::row_major> bh[2], bl[2];
#pragma unroll
    for (int nj = 0; nj < 2; nj++) {
        int n0 = warpN * 32 + nj * 16;
        wmma::load_matrix_sync(bh[nj], Bh + n0, SPB);
        wmma::load_matrix_sync(bl[nj], Bl + n0, SPB);
    }
#pragma unroll
    for (int mi = 0; mi < 4; mi++) {
        int m0 = warpM * 64 + mi * 16;
        wmma::fragment<wmma::matrix_a, 16, 16, 16, __half, wmma::row_major> ah, al;
        wmma::load_matrix_sync(ah, Ah + m0 * SPA, SPA);
        wmma::load_matrix_sync(al, Al + m0 * SPA, SPA);
#pragma unroll
        for (int nj = 0; nj < 2; nj++) {
            wmma::mma_sync(acc[mi][nj], ah, bh[nj], acc[mi][nj]);
            wmma::mma_sync(acc[mi][nj], ah, bl[nj], acc[mi][nj]);
            wmma::mma_sync(acc[mi][nj], al, bh[nj], acc[mi][nj]);
        }
    }
}
// A col-major ([k][m] tile, pitch SPB), B row-major
__device__ __forceinline__ void mma_colA(
    const __half* Ah, const __half* Al, const __half* Bh, const __half* Bl,
    wmma::fragment<wmma::accumulator, 16, 16, 16, float> acc[4][2],
    int warpM, int warpN)
{
    wmma::fragment<wmma::matrix_b, 16, 16, 16, __half, wmma::row_major> bh[2], bl[2];
#pragma unroll
    for (int nj = 0; nj < 2; nj++) {
        int n0 = warpN * 32 + nj * 16;
        wmma::load_matrix_sync(bh[nj], Bh + n0, SPB);
        wmma::load_matrix_sync(bl[nj], Bl + n0, SPB);
    }
#pragma unroll
    for (int mi = 0; mi < 4; mi++) {
        int m0 = warpM * 64 + mi * 16;
        wmma::fragment<wmma::matrix_a, 16, 16, 16, __half, wmma::col_major> ah, al;
        wmma::load_matrix_sync(ah, Ah + m0, SPB);
        wmma::load_matrix_sync(al, Al + m0, SPB);
#pragma unroll
        for (int nj = 0; nj < 2; nj++) {
            wmma::mma_sync(acc[mi][nj], ah, bh[nj], acc[mi][nj]);
            wmma::mma_sync(acc[mi][nj], ah, bl[nj], acc[mi][nj]);
            wmma::mma_sync(acc[mi][nj], al, bh[nj], acc[mi][nj]);
        }
    }
}

#define ACC_DECL                                                               \
    wmma::fragment<wmma::accumulator, 16, 16, 16, float> acc[4][2];            \
    _Pragma("unroll") for (int mi = 0; mi < 4; mi++)                           \
    _Pragma("unroll") for (int nj = 0; nj < 2; nj++)                           \
        wmma::fill_fragment(acc[mi][nj], 0.0f)

// ---------------- convert kernels ----------------
__global__ __launch_bounds__(256) void conv_x(const float4* __restrict__ x) {
    size_t i = (size_t)blockIdx.x * 256 + threadIdx.x;   // BL*DDIM/4
    float4 v = x[i];
    __half h[4], l[4];
    split2(v.x, h[0], l[0]); split2(v.y, h[1], l[1]);
    split2(v.z, h[2], l[2]); split2(v.w, h[3], l[3]);
    ((uint2*)g_xh)[i] = *(uint2*)h;
    ((uint2*)g_xl)[i] = *(uint2*)l;
}
__global__ __launch_bounds__(256) void conv_w(const float4* __restrict__ qw,
                                              const float4* __restrict__ kw) {
    size_t i = (size_t)blockIdx.x * 256 + threadIdx.x;   // DDIM*EDIM/4
    const float4* W = blockIdx.y ? kw : qw;
    __half* oh = blockIdx.y ? g_wkh : g_wqh;
    __half* ol = blockIdx.y ? g_wkl : g_wql;
    float4 v = W[i];
    __half h[4], l[4];
    split2(v.x * 256.0f, h[0], l[0]); split2(v.y * 256.0f, h[1], l[1]);
    split2(v.z * 256.0f, h[2], l[2]); split2(v.w * 256.0f, h[3], l[3]);
    ((uint2*)oh)[i] = *(uint2*)h;
    ((uint2*)ol)[i] = *(uint2*)l;
}

// ---------------- proj: grid (2, BL/128, 2) ----------------
__global__ __launch_bounds__(256, 2) void proj_kernel()
{
    __shared__ __align__(16) __half sA[2][2][128 * SPA];
    __shared__ __align__(16) __half sB[2][2][16 * SPB];
    const int tid = threadIdx.x, lane = tid & 31, wid = tid >> 5;
    const int warpM = wid >> 2, warpN = wid & 3;
    const int mBase = blockIdx.y * 128, nBase = blockIdx.x * 128;
    const __half* Ah = g_xh + (size_t)mBase * DDIM;           // [m][k]
    const __half* Al = g_xl + (size_t)mBase * DDIM;
    const __half* Bh = (blockIdx.z ? g_wkh : g_wqh) + nBase;  // [k][n]
    const __half* Bl = (blockIdx.z ? g_wkl : g_wql) + nBase;
    __half* Oh = blockIdx.z ? g_kh : g_qh;
    __half* Ol = blockIdx.z ? g_kl : g_ql;

    const int am = tid >> 1, ac = (tid & 1) * 8;       // A chunk
    const int bk = tid >> 4, bn = (tid & 15) * 8;      // B chunk
    const uint32_t dA0 = sptr(&sA[0][0][am * SPA + ac]);
    const uint32_t dA1 = sptr(&sA[0][1][am * SPA + ac]);
    const uint32_t dB0 = sptr(&sB[0][0][bk * SPB + bn]);
    const uint32_t dB1 = sptr(&sB[0][1][bk * SPB + bn]);
    const uint32_t stA = (uint32_t)(2 * 2 * 128 * SPA);  // bytes between stages
    const uint32_t stB = (uint32_t)(2 * 2 * 16 * SPB);

    ACC_DECL;
    const int NK = DDIM / 16;
    {   // prefetch stage 0
        CP16(dA0, Ah + (size_t)am * DDIM + ac);
        CP16(dA1, Al + (size_t)am * DDIM + ac);
        CP16(dB0, Bh + (size_t)bk * EDIM + bn);
        CP16(dB1, Bl + (size_t)bk * EDIM + bn);
        CP_COMMIT();
    }
    for (int t = 0; t < NK; t++) {
        if (t + 1 < NK) {
            int k0 = (t + 1) * 16, s = (t + 1) & 1;
            CP16(dA0 + s * stA, Ah + (size_t)am * DDIM + k0 + ac);
            CP16(dA1 + s * stA, Al + (size_t)am * DDIM + k0 + ac);
            CP16(dB0 + s * stB, Bh + (size_t)(k0 + bk) * EDIM + bn);
            CP16(dB1 + s * stB, Bl + (size_t)(k0 + bk) * EDIM + bn);
            CP_COMMIT();
            CP_WAIT1();
        } else {
            CP_WAIT0();
        }
        __syncthreads();
        int s = t & 1;
        mma_rowA(sA[s][0], sA[s][1], sB[s][0], sB[s][1], acc, warpM, warpN);
        __syncthreads();
    }

    // epilogue: v = exp(acc/256)/16, split hi/lo, coalesced write
    float* stage = reinterpret_cast<float*>(&sA[0][0][0]) + wid * 256;
    const float ie = 1.0f / 256.0f;
    const int r = lane >> 1, c0 = (lane & 1) * 8;
#pragma unroll
    for (int mi = 0; mi < 4; mi++)
#pragma unroll
        for (int nj = 0; nj < 2; nj++) {
            wmma::store_matrix_sync(stage, acc[mi][nj], 16, wmma::mem_row_major);
            __syncwarp();
            int rg = mBase + warpM * 64 + mi * 16 + r;
            int cg = nBase + warpN * 32 + nj * 16 + c0;
            __half hb[8], lb[8];
#pragma unroll
            for (int j = 0; j < 8; j++) {
                float v = expf(stage[r * 16 + c0 + j] * ie) * 0.0625f;
                split2(v, hb[j], lb[j]);
            }
            *(uint4*)(Oh + (size_t)rg * EDIM + cg) = *(uint4*)hb;
            *(uint4*)(Ol + (size_t)rg * EDIM + cg) = *(uint4*)lb;
            __syncwarp();
        }
}

// ---------------- zc: one warp per row ----------------
__global__ __launch_bounds__(256) void zc_kernel()
{
    int row = (int)((blockIdx.x * 256 + threadIdx.x) >> 5);
    int lane = threadIdx.x & 31;
    const __half2* ph = (const __half2*)(g_qh + (size_t)row * EDIM);
    const __half2* pl = (const __half2*)(g_ql + (size_t)row * EDIM);
    float s = 0.0f;
#pragma unroll
    for (int i = 0; i < 4; i++) {
        float2 h = __half22float2(ph[lane + 32 * i]);
        float2 l = __half22float2(pl[lane + 32 * i]);
        s += (h.x + h.y) + (l.x + l.y);
    }
#pragma unroll
    for (int o = 16; o; o >>= 1) s += __shfl_xor_sync(0xffffffffu, s, o);
    if (lane == 0) g_zc[row] = 4096.0f / (16.0f * s + 1e-8f);
}

// ---------------- kv: grid (8, 2, 8).  acc = (16k'')^T @ x = kv/16 ----------
__global__ __launch_bounds__(256, 2) void kv_kernel()
{
    __shared__ __align__(16) __half sA[2][2][16 * SPB];
    __shared__ __align__(16) __half sB[2][2][16 * SPB];
    const int tid = threadIdx.x, lane = tid & 31, wid = tid >> 5;
    const int warpM = wid >> 2, warpN = wid & 3;
    const int b = blockIdx.z;
    const int mBase = blockIdx.y * 128;   // e
    const int nBase = blockIdx.x * 128;   // d
    const __half* Ah = g_kh + (size_t)b * LSEQ * EDIM + mBase;  // [k=l][m=e]
    const __half* Al = g_kl + (size_t)b * LSEQ * EDIM + mBase;
    const __half* Bh = g_xh + (size_t)b * LSEQ * DDIM + nBase;  // [k=l][n=d]
    const __half* Bl = g_xl + (size_t)b * LSEQ * DDIM + nBase;

    const int bk = tid >> 4, bn = (tid & 15) * 8;
    const uint32_t dA0 = sptr(&sA[0][0][bk * SPB + bn]);
    const uint32_t dA1 = sptr(&sA[0][1][bk * SPB + bn]);
    const uint32_t dB0 = sptr(&sB[0][0][bk * SPB + bn]);
    const uint32_t dB1 = sptr(&sB[0][1][bk * SPB + bn]);
    const uint32_t stT = (uint32_t)(2 * 2 * 16 * SPB);

    ACC_DECL;
    const int NK = LSEQ / 16;
    CP16(dA0, Ah + (size_t)bk * EDIM + bn);
    CP16(dA1, Al + (size_t)bk * EDIM + bn);
    CP16(dB0, Bh + (size_t)bk * DDIM + bn);
    CP16(dB1, Bl + (size_t)bk * DDIM + bn);
    CP_COMMIT();
    for (int t = 0; t < NK; t++) {
        if (t + 1 < NK) {
            int k0 = (t + 1) * 16, s = (t + 1) & 1;
            CP16(dA0 + s * stT, Ah + (size_t)(k0 + bk) * EDIM + bn);
            CP16(dA1 + s * stT, Al + (size_t)(k0 + bk) * EDIM + bn);
            CP16(dB0 + s * stT, Bh + (size_t)(k0 + bk) * DDIM + bn);
            CP16(dB1 + s * stT, Bl + (size_t)(k0 + bk) * DDIM + bn);
            CP_COMMIT();
            CP_WAIT1();
        } else {
            CP_WAIT0();
        }
        __syncthreads();
        int s = t & 1;
        mma_colA(sA[s][0], sA[s][1], sB[s][0], sB[s][1], acc, warpM, warpN);
        __syncthreads();
    }

    // epilogue: kvh/kvl = split(acc/16) = split(kv/256)
    float* stage = reinterpret_cast<float*>(&sA[0][0][0]) + wid * 256;
    __half* Oh = g_kvh + (size_t)b * EDIM * DDIM;
    __half* Ol = g_kvl + (size_t)b * EDIM * DDIM;
    const int r = lane >> 1, c0 = (lane & 1) * 8;
#pragma unroll
    for (int mi = 0; mi < 4; mi++)
#pragma unroll
        for (int nj = 0; nj < 2; nj++) {
            wmma::store_matrix_sync(stage, acc[mi][nj], 16, wmma::mem_row_major);
            __syncwarp();
            int rg = mBase + warpM * 64 + mi * 16 + r;
            int cg = nBase + warpN * 32 + nj * 16 + c0;
            __half hb[8], lb[8];
#pragma unroll
            for (int j = 0; j < 8; j++)
                split2(stage[r * 16 + c0 + j] * 0.0625f, hb[j], lb[j]);
            *(uint4*)(Oh + (size_t)rg * DDIM + cg) = *(uint4*)hb;
            *(uint4*)(Ol + (size_t)rg * DDIM + cg) = *(uint4*)lb;
            __syncwarp();
        }
}

// ---------------- num: grid (8, 32, 8).  out = acc * zc[l] ----------------
__global__ __launch_bounds__(256, 2) void num_kernel(float* __restrict__ out)
{
    __shared__ __align__(16) __half sA[2][2][128 * SPA];
    __shared__ __align__(16) __half sB[2][2][16 * SPB];
    const int tid = threadIdx.x, lane = tid & 31, wid = tid >> 5;
    const int warpM = wid >> 2, warpN = wid & 3;
    const int b = blockIdx.z;
    const int mBase = blockIdx.y * 128;   // l
    const int nBase = blockIdx.x * 128;   // d
    const __half* Ah = g_qh + ((size_t)b * LSEQ + mBase) * EDIM;  // [m=l][k=e]
    const __half* Al = g_ql + ((size_t)b * LSEQ + mBase) * EDIM;
    const __half* Bh = g_kvh + (size_t)b * EDIM * DDIM + nBase;   // [k=e][n=d]
    const __half* Bl = g_kvl + (size_t)b * EDIM * DDIM + nBase;

    const int am = tid >> 1, ac = (tid & 1) * 8;
    const int bk = tid >> 4, bn = (tid & 15) * 8;
    const uint32_t dA0 = sptr(&sA[0][0][am * SPA + ac]);
    const uint32_t dA1 = sptr(&sA[0][1][am * SPA + ac]);
    const uint32_t dB0 = sptr(&sB[0][0][bk * SPB + bn]);
    const uint32_t dB1 = sptr(&sB[0][1][bk * SPB + bn]);
    const uint32_t stA = (uint32_t)(2 * 2 * 128 * SPA);
    const uint32_t stB = (uint32_t)(2 * 2 * 16 * SPB);

    ACC_DECL;
    const int NK = EDIM / 16;
    CP16(dA0, Ah + (size_t)am * EDIM + ac);
    CP16(dA1, Al + (size_t)am * EDIM + ac);
    CP16(dB0, Bh + (size_t)bk * DDIM + bn);
    CP16(dB1, Bl + (size_t)bk * DDIM + bn);
    CP_COMMIT();
    for (int t = 0; t < NK; t++) {
        if (t + 1 < NK) {
            int k0 = (t + 1) * 16, s = (t + 1) & 1;
            CP16(dA0 + s * stA, Ah + (size_t)am * EDIM + k0 + ac);
            CP16(dA1 + s * stA, Al + (size_t)am * EDIM + k0 + ac);
            CP16(dB0 + s * stB, Bh + (size_t)(k0 + bk) * DDIM + bn);
            CP16(dB1 + s * stB, Bl + (size_t)(k0 + bk) * DDIM + bn);
            CP_COMMIT();
            CP_WAIT1();
        } else {
            CP_WAIT0();
        }
        __syncthreads();
        int s = t & 1;
        mma_rowA(sA[s][0], sA[s][1], sB[s][0], sB[s][1], acc, warpM, warpN);
        __syncthreads();
    }

    // epilogue: out = acc * zc[row]
    float* stage = reinterpret_cast<float*>(&sA[0][0][0]) + wid * 256;
    float* O = out + (size_t)b * LSEQ * DDIM;
    const int r = lane >> 1, c0 = (lane & 1) * 8;
#pragma unroll
    for (int mi = 0; mi < 4; mi++)
#pragma unroll
        for (int nj = 0; nj < 2; nj++) {
            wmma::store_matrix_sync(stage, acc[mi][nj], 16, wmma::mem_row_major);
            __syncwarp();
            int rg = mBase + warpM * 64 + mi * 16 + r;
            int cg = nBase + warpN * 32 + nj * 16 + c0;
            float zc = g_zc[b * LSEQ + rg];
            float ob[8];
#pragma unroll
            for (int j = 0; j < 8; j++)
                ob[j] = stage[r * 16 + c0 + j] * zc;
            *(float4*)(O + (size_t)rg * DDIM + cg)     = *(float4*)&ob[0];
            *(float4*)(O + (size_t)rg * DDIM + cg + 4) = *(float4*)&ob[4];
            __syncwarp();
        }
}

// ---------------- launch ----------------
extern "C" void kernel_launch(void* const* d_in, const int* in_sizes, int n_in,
                              void* d_out, int out_size)
{
    const float* x  = (const float*)d_in[0];
    const float* qw = (const float*)d_in[1];
    const float* kw = (const float*)d_in[2];
    float* out = (float*)d_out;

    conv_x<<<(int)((size_t)BL * DDIM / 4 / 256), 256>>>((const float4*)x);
    conv_w<<<dim3(DDIM * EDIM / 4 / 256, 2), 256>>>((const float4*)qw,
                                                    (const float4*)kw);
    proj_kernel<<<dim3(EDIM / 128, BL / 128, 2), 256>>>();
    zc_kernel<<<BL / 8, 256>>>();
    kv_kernel<<<dim3(DDIM / 128, EDIM / 128, BATCH), 256>>>();
    num_kernel<<<dim3(DDIM / 128, LSEQ / 128, BATCH), 256>>>(out);
}

// round 12
// speedup vs baseline: 1.3709x; 1.3709x over previous
#include <cuda_runtime.h>
#include <cuda_fp16.h>
#include <mma.h>
#include <math.h>
#include <stdint.h>

using namespace nvcuda;

// Linear attention, wmma m16n16k16 + 3xFP16 hi/lo splitting.
// R12: 128x64 block tile (acc=32 regs/thread) so __launch_bounds__(256,2)
// holds WITHOUT register spill; cp.async contiguous fills; wmma-native
// operand orientations (no transposed smem fills).
//   conv:  xh/xl = split(x);  wh/wl = split(256*W)
//   proj:  acc = x @ 256W;  qh/ql = split(exp(acc/256)/16) = split(16*q'')
//   zc  :  zc[l] = 4096 / (16*sum(qh+ql) + 1e-8)
//   kv  :  acc = (16k'')^T @ x = kv/16;  kvh/kvl = split(acc/16) = split(kv/256)
//   num :  acc = (16q'') @ (kv/256) = q'*kv/4096;  out = acc * zc[l]

#define BATCH 8
#define LSEQ  4096
#define DDIM  1024
#define EDIM  256
#define BL    (BATCH * LSEQ)
#define SPA   24    // A row-major tile pitch: 16 data + 8 pad halves
#define SPB   72    // B tile pitch: 64 data + 8 pad halves
#define SPK   136   // kv A col-major tile pitch: 128 data + 8 pad halves

// ---- scratch ----
__device__ __align__(16) __half g_xh[(size_t)BL * DDIM];   // [l][d]
__device__ __align__(16) __half g_xl[(size_t)BL * DDIM];
__device__ __align__(16) __half g_wqh[DDIM * EDIM];        // [d][e], 256W
__device__ __align__(16) __half g_wql[DDIM * EDIM];
__device__ __align__(16) __half g_wkh[DDIM * EDIM];
__device__ __align__(16) __half g_wkl[DDIM * EDIM];
__device__ __align__(16) __half g_qh[(size_t)BL * EDIM];   // [l][e], 16q''
__device__ __align__(16) __half g_ql[(size_t)BL * EDIM];
__device__ __align__(16) __half g_kh[(size_t)BL * EDIM];
__device__ __align__(16) __half g_kl[(size_t)BL * EDIM];
__device__ __align__(16) __half g_kvh[(size_t)BATCH * EDIM * DDIM];  // [b][e][d]
__device__ __align__(16) __half g_kvl[(size_t)BATCH * EDIM * DDIM];
__device__ float g_zc[BL];

// ---------------- helpers ----------------
__device__ __forceinline__ void split2(float x, __half& h, __half& l) {
    h = __float2half_rn(x);
    l = __float2half_rn(x - __half2float(h));
}
__device__ __forceinline__ uint32_t sptr(const void* p) {
    return (uint32_t)__cvta_generic_to_shared(p);
}
#define CP16(dst, src) \
    asm volatile("cp.async.cg.shared.global [%0], [%1], 16;" :: "r"(dst), "l"(src))
#define CP_COMMIT() asm volatile("cp.async.commit_group;")
#define CP_WAIT1()  asm volatile("cp.async.wait_group 1;")
#define CP_WAIT0()  asm volatile("cp.async.wait_group 0;")

#define ACC_DECL                                                               \
    wmma::fragment<wmma::accumulator, 16, 16, 16, float> acc[2][2];            \
    _Pragma("unroll") for (int mi = 0; mi < 2; mi++)                           \
    _Pragma("unroll") for (int nj = 0; nj < 2; nj++)                           \
        wmma::fill_fragment(acc[mi][nj], 0.0f)

// A row-major ([m][k] tile pitch SPA); warp tile 32x32 at (warpM, warpN)
__device__ __forceinline__ void mma_rowA(
    const __half* Ah, const __half* Al, const __half* Bh, const __half* Bl,
    wmma::fragment<wmma::accumulator, 16, 16, 16, float> acc[2][2],
    int warpM, int warpN)
{
    wmma::fragment<wmma::matrix_b, 16, 16, 16, __half, wmma::row_major> bh[2], bl[2];
#pragma unroll
    for (int nj = 0; nj < 2; nj++) {
        int n0 = warpN * 32 + nj * 16;
        wmma::load_matrix_sync(bh[nj], Bh + n0, SPB);
        wmma::load_matrix_sync(bl[nj], Bl + n0, SPB);
    }
#pragma unroll
    for (int mi = 0; mi < 2; mi++) {
        int m0 = warpM * 32 + mi * 16;
        wmma::fragment<wmma::matrix_a, 16, 16, 16, __half, wmma::row_major> ah, al;
        wmma::load_matrix_sync(ah, Ah + m0 * SPA, SPA);
        wmma::load_matrix_sync(al, Al + m0 * SPA, SPA);
#pragma unroll
        for (int nj = 0; nj < 2; nj++) {
            wmma::mma_sync(acc[mi][nj], ah, bh[nj], acc[mi][nj]);
            wmma::mma_sync(acc[mi][nj], ah, bl[nj], acc[mi][nj]);
            wmma::mma_sync(acc[mi][nj], al, bh[nj], acc[mi][nj]);
        }
    }
}
// A col-major ([k][m] tile pitch SPK)
__device__ __forceinline__ void mma_colA(
    const __half* Ah, const __half* Al, const __half* Bh, const __half* Bl,
    wmma::fragment<wmma::accumulator, 16, 16, 16, float> acc[2][2],
    int warpM, int warpN)
{
    wmma::fragment<wmma::matrix_b, 16, 16, 16, __half, wmma::row_major> bh[2], bl[2];
#pragma unroll
    for (int nj = 0; nj < 2; nj++) {
        int n0 = warpN * 32 + nj * 16;
        wmma::load_matrix_sync(bh[nj], Bh + n0, SPB);
        wmma::load_matrix_sync(bl[nj], Bl + n0, SPB);
    }
#pragma unroll
    for (int mi = 0; mi < 2; mi++) {
        int m0 = warpM * 32 + mi * 16;
        wmma::fragment<wmma::matrix_a, 16, 16, 16, __half, wmma::col_major> ah, al;
        wmma::load_matrix_sync(ah, Ah + m0, SPK);
        wmma::load_matrix_sync(al, Al + m0, SPK);
#pragma unroll
        for (int nj = 0; nj < 2; nj++) {
            wmma::mma_sync(acc[mi][nj], ah, bh[nj], acc[mi][nj]);
            wmma::mma_sync(acc[mi][nj], ah, bl[nj], acc[mi][nj]);
            wmma::mma_sync(acc[mi][nj], al, bh[nj], acc[mi][nj]);
        }
    }
}

// ---------------- convert kernels ----------------
__global__ __launch_bounds__(256) void conv_x(const float4* __restrict__ x) {
    size_t i = (size_t)blockIdx.x * 256 + threadIdx.x;   // BL*DDIM/4
    float4 v = x[i];
    __half h[4], l[4];
    split2(v.x, h[0], l[0]); split2(v.y, h[1], l[1]);
    split2(v.z, h[2], l[2]); split2(v.w, h[3], l[3]);
    ((uint2*)g_xh)[i] = *(uint2*)h;
    ((uint2*)g_xl)[i] = *(uint2*)l;
}
__global__ __launch_bounds__(256) void conv_w(const float4* __restrict__ qw,
                                              const float4* __restrict__ kw) {
    size_t i = (size_t)blockIdx.x * 256 + threadIdx.x;   // DDIM*EDIM/4
    const float4* W = blockIdx.y ? kw : qw;
    __half* oh = blockIdx.y ? g_wkh : g_wqh;
    __half* ol = blockIdx.y ? g_wkl : g_wql;
    float4 v = W[i];
    __half h[4], l[4];
    split2(v.x * 256.0f, h[0], l[0]); split2(v.y * 256.0f, h[1], l[1]);
    split2(v.z * 256.0f, h[2], l[2]); split2(v.w * 256.0f, h[3], l[3]);
    ((uint2*)oh)[i] = *(uint2*)h;
    ((uint2*)ol)[i] = *(uint2*)l;
}

// ---------------- proj: grid (EDIM/64=4, BL/128=256, 2) ----------------
__global__ __launch_bounds__(256, 2) void proj_kernel()
{
    __shared__ __align__(16) __half sA[2][2][128 * SPA];
    __shared__ __align__(16) __half sB[2][2][16 * SPB];
    const int tid = threadIdx.x, lane = tid & 31, wid = tid >> 5;
    const int warpM = wid >> 1, warpN = wid & 1;
    const int mBase = blockIdx.y * 128, nBase = blockIdx.x * 64;
    const __half* Ah = g_xh + (size_t)mBase * DDIM;           // [m][k]
    const __half* Al = g_xl + (size_t)mBase * DDIM;
    const __half* Bh = (blockIdx.z ? g_wkh : g_wqh) + nBase;  // [k][n]
    const __half* Bl = (blockIdx.z ? g_wkl : g_wql) + nBase;
    __half* Oh = blockIdx.z ? g_kh : g_qh;
    __half* Ol = blockIdx.z ? g_kl : g_ql;

    const int am = tid >> 1, ac = (tid & 1) * 8;      // 256 thr: A 128x16
    const int bk = tid >> 3, bn = (tid & 7) * 8;      // 128 thr: B 16x64
    const uint32_t dA0 = sptr(&sA[0][0][am * SPA + ac]);
    const uint32_t dA1 = sptr(&sA[0][1][am * SPA + ac]);
    const uint32_t dB0 = sptr(&sB[0][0][bk * SPB + bn]);
    const uint32_t dB1 = sptr(&sB[0][1][bk * SPB + bn]);
    const uint32_t stA = (uint32_t)(2 * 2 * 128 * SPA);
    const uint32_t stB = (uint32_t)(2 * 2 * 16 * SPB);

    ACC_DECL;
    const int NK = DDIM / 16;
    CP16(dA0, Ah + (size_t)am * DDIM + ac);
    CP16(dA1, Al + (size_t)am * DDIM + ac);
    if (tid < 128) {
        CP16(dB0, Bh + (size_t)bk * EDIM + bn);
        CP16(dB1, Bl + (size_t)bk * EDIM + bn);
    }
    CP_COMMIT();
    for (int t = 0; t < NK; t++) {
        if (t + 1 < NK) {
            int k0 = (t + 1) * 16, s = (t + 1) & 1;
            CP16(dA0 + s * stA, Ah + (size_t)am * DDIM + k0 + ac);
            CP16(dA1 + s * stA, Al + (size_t)am * DDIM + k0 + ac);
            if (tid < 128) {
                CP16(dB0 + s * stB, Bh + (size_t)(k0 + bk) * EDIM + bn);
                CP16(dB1 + s * stB, Bl + (size_t)(k0 + bk) * EDIM + bn);
            }
            CP_COMMIT();
            CP_WAIT1();
        } else {
            CP_WAIT0();
        }
        __syncthreads();
        int s = t & 1;
        mma_rowA(sA[s][0], sA[s][1], sB[s][0], sB[s][1], acc, warpM, warpN);
        __syncthreads();
    }

    // epilogue: v = exp(acc/256)/16, split hi/lo, coalesced write
    float* stage = reinterpret_cast<float*>(&sA[0][0][0]) + wid * 256;
    const float ie = 1.0f / 256.0f;
    const int r = lane >> 1, c0 = (lane & 1) * 8;
#pragma unroll
    for (int mi = 0; mi < 2; mi++)
#pragma unroll
        for (int nj = 0; nj < 2; nj++) {
            wmma::store_matrix_sync(stage, acc[mi][nj], 16, wmma::mem_row_major);
            __syncwarp();
            int rg = mBase + warpM * 32 + mi * 16 + r;
            int cg = nBase + warpN * 32 + nj * 16 + c0;
            __half hb[8], lb[8];
#pragma unroll
            for (int j = 0; j < 8; j++) {
                float v = expf(stage[r * 16 + c0 + j] * ie) * 0.0625f;
                split2(v, hb[j], lb[j]);
            }
            *(uint4*)(Oh + (size_t)rg * EDIM + cg) = *(uint4*)hb;
            *(uint4*)(Ol + (size_t)rg * EDIM + cg) = *(uint4*)lb;
            __syncwarp();
        }
}

// ---------------- zc: one warp per row ----------------
__global__ __launch_bounds__(256) void zc_kernel()
{
    int row = (int)((blockIdx.x * 256 + threadIdx.x) >> 5);
    int lane = threadIdx.x & 31;
    const __half2* ph = (const __half2*)(g_qh + (size_t)row * EDIM);
    const __half2* pl = (const __half2*)(g_ql + (size_t)row * EDIM);
    float s = 0.0f;
#pragma unroll
    for (int i = 0; i < 4; i++) {
        float2 h = __half22float2(ph[lane + 32 * i]);
        float2 l = __half22float2(pl[lane + 32 * i]);
        s += (h.x + h.y) + (l.x + l.y);
    }
#pragma unroll
    for (int o = 16; o; o >>= 1) s += __shfl_xor_sync(0xffffffffu, s, o);
    if (lane == 0) g_zc[row] = 4096.0f / (16.0f * s + 1e-8f);
}

// ---------------- kv: grid (DDIM/64=16, EDIM/128=2, 8) ----------------
__global__ __launch_bounds__(256, 2) void kv_kernel()
{
    __shared__ __align__(16) __half sA[2][2][16 * SPK];
    __shared__ __align__(16) __half sB[2][2][16 * SPB];
    const int tid = threadIdx.x, lane = tid & 31, wid = tid >> 5;
    const int warpM = wid >> 1, warpN = wid & 1;
    const int b = blockIdx.z;
    const int mBase = blockIdx.y * 128;   // e
    const int nBase = blockIdx.x * 64;    // d
    const __half* Ah = g_kh + (size_t)b * LSEQ * EDIM + mBase;  // [k=l][m=e]
    const __half* Al = g_kl + (size_t)b * LSEQ * EDIM + mBase;
    const __half* Bh = g_xh + (size_t)b * LSEQ * DDIM + nBase;  // [k=l][n=d]
    const __half* Bl = g_xl + (size_t)b * LSEQ * DDIM + nBase;

    const int ak = tid >> 4, an = (tid & 15) * 8;     // 256 thr: A 16x128
    const int bk = tid >> 3, bn = (tid & 7) * 8;      // 128 thr: B 16x64
    const uint32_t dA0 = sptr(&sA[0][0][ak * SPK + an]);
    const uint32_t dA1 = sptr(&sA[0][1][ak * SPK + an]);
    const uint32_t dB0 = sptr(&sB[0][0][bk * SPB + bn]);
    const uint32_t dB1 = sptr(&sB[0][1][bk * SPB + bn]);
    const uint32_t stA = (uint32_t)(2 * 2 * 16 * SPK);
    const uint32_t stB = (uint32_t)(2 * 2 * 16 * SPB);

    ACC_DECL;
    const int NK = LSEQ / 16;
    CP16(dA0, Ah + (size_t)ak * EDIM + an);
    CP16(dA1, Al + (size_t)ak * EDIM + an);
    if (tid < 128) {
        CP16(dB0, Bh + (size_t)bk * DDIM + bn);
        CP16(dB1, Bl + (size_t)bk * DDIM + bn);
    }
    CP_COMMIT();
    for (int t = 0; t < NK; t++) {
        if (t + 1 < NK) {
            int k0 = (t + 1) * 16, s = (t + 1) & 1;
            CP16(dA0 + s * stA, Ah + (size_t)(k0 + ak) * EDIM + an);
            CP16(dA1 + s * stA, Al + (size_t)(k0 + ak) * EDIM + an);
            if (tid < 128) {
                CP16(dB0 + s * stB, Bh + (size_t)(k0 + bk) * DDIM + bn);
                CP16(dB1 + s * stB, Bl + (size_t)(k0 + bk) * DDIM + bn);
            }
            CP_COMMIT();
            CP_WAIT1();
        } else {
            CP_WAIT0();
        }
        __syncthreads();
        int s = t & 1;
        mma_colA(sA[s][0], sA[s][1], sB[s][0], sB[s][1], acc, warpM, warpN);
        __syncthreads();
    }

    // epilogue: kvh/kvl = split(acc/16) = split(kv/256)
    float* stage = reinterpret_cast<float*>(&sA[0][0][0]) + wid * 256;
    __half* Oh = g_kvh + (size_t)b * EDIM * DDIM;
    __half* Ol = g_kvl + (size_t)b * EDIM * DDIM;
    const int r = lane >> 1, c0 = (lane & 1) * 8;
#pragma unroll
    for (int mi = 0; mi < 2; mi++)
#pragma unroll
        for (int nj = 0; nj < 2; nj++) {
            wmma::store_matrix_sync(stage, acc[mi][nj], 16, wmma::mem_row_major);
            __syncwarp();
            int rg = mBase + warpM * 32 + mi * 16 + r;
            int cg = nBase + warpN * 32 + nj * 16 + c0;
            __half hb[8], lb[8];
#pragma unroll
            for (int j = 0; j < 8; j++)
                split2(stage[r * 16 + c0 + j] * 0.0625f, hb[j], lb[j]);
            *(uint4*)(Oh + (size_t)rg * DDIM + cg) = *(uint4*)hb;
            *(uint4*)(Ol + (size_t)rg * DDIM + cg) = *(uint4*)lb;
            __syncwarp();
        }
}

// ---------------- num: grid (16, 32, 8).  out = acc * zc[l] ----------------
__global__ __launch_bounds__(256, 2) void num_kernel(float* __restrict__ out)
{
    __shared__ __align__(16) __half sA[2][2][128 * SPA];
    __shared__ __align__(16) __half sB[2][2][16 * SPB];
    const int tid = threadIdx.x, lane = tid & 31, wid = tid >> 5;
    const int warpM = wid >> 1, warpN = wid & 1;
    const int b = blockIdx.z;
    const int mBase = blockIdx.y * 128;   // l
    const int nBase = blockIdx.x * 64;    // d
    const __half* Ah = g_qh + ((size_t)b * LSEQ + mBase) * EDIM;  // [m=l][k=e]
    const __half* Al = g_ql + ((size_t)b * LSEQ + mBase) * EDIM;
    const __half* Bh = g_kvh + (size_t)b * EDIM * DDIM + nBase;   // [k=e][n=d]
    const __half* Bl = g_kvl + (size_t)b * EDIM * DDIM + nBase;

    const int am = tid >> 1, ac = (tid & 1) * 8;
    const int bk = tid >> 3, bn = (tid & 7) * 8;
    const uint32_t dA0 = sptr(&sA[0][0][am * SPA + ac]);
    const uint32_t dA1 = sptr(&sA[0][1][am * SPA + ac]);
    const uint32_t dB0 = sptr(&sB[0][0][bk * SPB + bn]);
    const uint32_t dB1 = sptr(&sB[0][1][bk * SPB + bn]);
    const uint32_t stA = (uint32_t)(2 * 2 * 128 * SPA);
    const uint32_t stB = (uint32_t)(2 * 2 * 16 * SPB);

    ACC_DECL;
    const int NK = EDIM / 16;
    CP16(dA0, Ah + (size_t)am * EDIM + ac);
    CP16(dA1, Al + (size_t)am * EDIM + ac);
    if (tid < 128) {
        CP16(dB0, Bh + (size_t)bk * DDIM + bn);
        CP16(dB1, Bl + (size_t)bk * DDIM + bn);
    }
    CP_COMMIT();
    for (int t = 0; t < NK; t++) {
        if (t + 1 < NK) {
            int k0 = (t + 1) * 16, s = (t + 1) & 1;
            CP16(dA0 + s * stA, Ah + (size_t)am * EDIM + k0 + ac);
            CP16(dA1 + s * stA, Al + (size_t)am * EDIM + k0 + ac);
            if (tid < 128) {
                CP16(dB0 + s * stB, Bh + (size_t)(k0 + bk) * DDIM + bn);
                CP16(dB1 + s * stB, Bl + (size_t)(k0 + bk) * DDIM + bn);
            }
            CP_COMMIT();
            CP_WAIT1();
        } else {
            CP_WAIT0();
        }
        __syncthreads();
        int s = t & 1;
        mma_rowA(sA[s][0], sA[s][1], sB[s][0], sB[s][1], acc, warpM, warpN);
        __syncthreads();
    }

    // epilogue: out = acc * zc[row]
    float* stage = reinterpret_cast<float*>(&sA[0][0][0]) + wid * 256;
    float* O = out + (size_t)b * LSEQ * DDIM;
    const int r = lane >> 1, c0 = (lane & 1) * 8;
#pragma unroll
    for (int mi = 0; mi < 2; mi++)
#pragma unroll
        for (int nj = 0; nj < 2; nj++) {
            wmma::store_matrix_sync(stage, acc[mi][nj], 16, wmma::mem_row_major);
            __syncwarp();
            int rg = mBase + warpM * 32 + mi * 16 + r;
            int cg = nBase + warpN * 32 + nj * 16 + c0;
            float zc = g_zc[b * LSEQ + rg];
            float ob[8];
#pragma unroll
            for (int j = 0; j < 8; j++)
                ob[j] = stage[r * 16 + c0 + j] * zc;
            *(float4*)(O + (size_t)rg * DDIM + cg)     = *(float4*)&ob[0];
            *(float4*)(O + (size_t)rg * DDIM + cg + 4) = *(float4*)&ob[4];
            __syncwarp();
        }
}

// ---------------- launch ----------------
extern "C" void kernel_launch(void* const* d_in, const int* in_sizes, int n_in,
                              void* d_out, int out_size)
{
    const float* x  = (const float*)d_in[0];
    const float* qw = (const float*)d_in[1];
    const float* kw = (const float*)d_in[2];
    float* out = (float*)d_out;

    conv_x<<<(int)((size_t)BL * DDIM / 4 / 256), 256>>>((const float4*)x);
    conv_w<<<dim3(DDIM * EDIM / 4 / 256, 2), 256>>>((const float4*)qw,
                                                    (const float4*)kw);
    proj_kernel<<<dim3(EDIM / 64, BL / 128, 2), 256>>>();
    zc_kernel<<<BL / 8, 256>>>();
    kv_kernel<<<dim3(DDIM / 64, EDIM / 128, BATCH), 256>>>();
    num_kernel<<<dim3(DDIM / 64, LSEQ / 128, BATCH), 256>>>(out);
}

// round 13
// speedup vs baseline: 1.5520x; 1.1321x over previous
#include <cuda_runtime.h>
#include <cuda_fp16.h>
#include <mma.h>
#include <math.h>
#include <stdint.h>

using namespace nvcuda;

// Linear attention, wmma m16n16k16 + 3xFP16 hi/lo splitting.
// R13: BK=32 chunks (2 k-steps per sync window) enabled by DYNAMIC shared
// memory (59KB/CTA > 48KB static limit), keeping __launch_bounds__(256,2).
// Otherwise identical to R12 (128x64 tiles, cp.async fills, native layouts).
//   conv:  xh/xl = split(x);  wh/wl = split(256*W)
//   proj:  acc = x @ 256W;  qh/ql = split(exp(acc/256)/16) = split(16*q'')
//   zc  :  zc[l] = 4096 / (16*sum(qh+ql) + 1e-8)
//   kv  :  acc = (16k'')^T @ x = kv/16;  kvh/kvl = split(acc/16) = split(kv/256)
//   num :  acc = (16q'') @ (kv/256) = q'*kv/4096;  out = acc * zc[l]

#define BATCH 8
#define LSEQ  4096
#define DDIM  1024
#define EDIM  256
#define BL    (BATCH * LSEQ)
#define SPA   40    // A row-major tile pitch: 32 data + 8 pad halves
#define SPB   72    // B tile pitch: 64 data + 8 pad halves
#define SPK   136   // kv A col-major tile pitch: 128 data + 8 pad halves

// dynamic smem layout (bytes)
#define A_HL    (128 * SPA * 2)          // one hi or lo A buffer: 10240
#define ASTAGE  (2 * A_HL)               // hi+lo per stage: 20480
#define SBOFF   (2 * ASTAGE)             // B region starts after 2 A stages
#define B_HL    (32 * SPB * 2)           // 4608
#define BSTAGE  (2 * B_HL)               // 9216
#define SMEM_PN (SBOFF + 2 * BSTAGE)     // proj/num: 59392
#define AK_HL   (32 * SPK * 2)           // kv A buffer: 8704
#define AKSTAGE (2 * AK_HL)              // 17408
#define SBOFF_K (2 * AKSTAGE)            // 34816
#define SMEM_KV (SBOFF_K + 2 * BSTAGE)   // 53248

// ---- scratch ----
__device__ __align__(16) __half g_xh[(size_t)BL * DDIM];   // [l][d]
__device__ __align__(16) __half g_xl[(size_t)BL * DDIM];
__device__ __align__(16) __half g_wqh[DDIM * EDIM];        // [d][e], 256W
__device__ __align__(16) __half g_wql[DDIM * EDIM];
__device__ __align__(16) __half g_wkh[DDIM * EDIM];
__device__ __align__(16) __half g_wkl[DDIM * EDIM];
__device__ __align__(16) __half g_qh[(size_t)BL * EDIM];   // [l][e], 16q''
__device__ __align__(16) __half g_ql[(size_t)BL * EDIM];
__device__ __align__(16) __half g_kh[(size_t)BL * EDIM];
__device__ __align__(16) __half g_kl[(size_t)BL * EDIM];
__device__ __align__(16) __half g_kvh[(size_t)BATCH * EDIM * DDIM];  // [b][e][d]
__device__ __align__(16) __half g_kvl[(size_t)BATCH * EDIM * DDIM];
__device__ float g_zc[BL];

// ---------------- helpers ----------------
__device__ __forceinline__ void split2(float x, __half& h, __half& l) {
    h = __float2half_rn(x);
    l = __float2half_rn(x - __half2float(h));
}
__device__ __forceinline__ uint32_t sptr(const void* p) {
    return (uint32_t)__cvta_generic_to_shared(p);
}
#define CP16(dst, src) \
    asm volatile("cp.async.cg.shared.global [%0], [%1], 16;" :: "r"(dst), "l"(src))
#define CP_COMMIT() asm volatile("cp.async.commit_group;")
#define CP_WAIT1()  asm volatile("cp.async.wait_group 1;")
#define CP_WAIT0()  asm volatile("cp.async.wait_group 0;")

#define ACC_DECL                                                               \
    wmma::fragment<wmma::accumulator, 16, 16, 16, float> acc[2][2];            \
    _Pragma("unroll") for (int mi = 0; mi < 2; mi++)                           \
    _Pragma("unroll") for (int nj = 0; nj < 2; nj++)                           \
        wmma::fill_fragment(acc[mi][nj], 0.0f)

// A row-major ([m][32k] pitch SPA), B ([32k][n] pitch SPB); 2 k-steps.
__device__ __forceinline__ void mma_rowA32(
    const __half* Ah, const __half* Al, const __half* Bh, const __half* Bl,
    wmma::fragment<wmma::accumulator, 16, 16, 16, float> acc[2][2],
    int warpM, int warpN)
{
#pragma unroll
    for (int kk = 0; kk < 32; kk += 16) {
        wmma::fragment<wmma::matrix_b, 16, 16, 16, __half, wmma::row_major> bh[2], bl[2];
#pragma unroll
        for (int nj = 0; nj < 2; nj++) {
            int n0 = warpN * 32 + nj * 16;
            wmma::load_matrix_sync(bh[nj], Bh + kk * SPB + n0, SPB);
            wmma::load_matrix_sync(bl[nj], Bl + kk * SPB + n0, SPB);
        }
#pragma unroll
        for (int mi = 0; mi < 2; mi++) {
            int m0 = warpM * 32 + mi * 16;
            wmma::fragment<wmma::matrix_a, 16, 16, 16, __half, wmma::row_major> ah, al;
            wmma::load_matrix_sync(ah, Ah + m0 * SPA + kk, SPA);
            wmma::load_matrix_sync(al, Al + m0 * SPA + kk, SPA);
#pragma unroll
            for (int nj = 0; nj < 2; nj++) {
                wmma::mma_sync(acc[mi][nj], ah, bh[nj], acc[mi][nj]);
                wmma::mma_sync(acc[mi][nj], ah, bl[nj], acc[mi][nj]);
                wmma::mma_sync(acc[mi][nj], al, bh[nj], acc[mi][nj]);
            }
        }
    }
}
// A col-major ([32k][m] pitch SPK)
__device__ __forceinline__ void mma_colA32(
    const __half* Ah, const __half* Al, const __half* Bh, const __half* Bl,
    wmma::fragment<wmma::accumulator, 16, 16, 16, float> acc[2][2],
    int warpM, int warpN)
{
#pragma unroll
    for (int kk = 0; kk < 32; kk += 16) {
        wmma::fragment<wmma::matrix_b, 16, 16, 16, __half, wmma::row_major> bh[2], bl[2];
#pragma unroll
        for (int nj = 0; nj < 2; nj++) {
            int n0 = warpN * 32 + nj * 16;
            wmma::load_matrix_sync(bh[nj], Bh + kk * SPB + n0, SPB);
            wmma::load_matrix_sync(bl[nj], Bl + kk * SPB + n0, SPB);
        }
#pragma unroll
        for (int mi = 0; mi < 2; mi++) {
            int m0 = warpM * 32 + mi * 16;
            wmma::fragment<wmma::matrix_a, 16, 16, 16, __half, wmma::col_major> ah, al;
            wmma::load_matrix_sync(ah, Ah + kk * SPK + m0, SPK);
            wmma::load_matrix_sync(al, Al + kk * SPK + m0, SPK);
#pragma unroll
            for (int nj = 0; nj < 2; nj++) {
                wmma::mma_sync(acc[mi][nj], ah, bh[nj], acc[mi][nj]);
                wmma::mma_sync(acc[mi][nj], ah, bl[nj], acc[mi][nj]);
                wmma::mma_sync(acc[mi][nj], al, bh[nj], acc[mi][nj]);
            }
        }
    }
}

// ---------------- convert kernels ----------------
__global__ __launch_bounds__(256) void conv_x(const float4* __restrict__ x) {
    size_t i = (size_t)blockIdx.x * 256 + threadIdx.x;   // BL*DDIM/4
    float4 v = x[i];
    __half h[4], l[4];
    split2(v.x, h[0], l[0]); split2(v.y, h[1], l[1]);
    split2(v.z, h[2], l[2]); split2(v.w, h[3], l[3]);
    ((uint2*)g_xh)[i] = *(uint2*)h;
    ((uint2*)g_xl)[i] = *(uint2*)l;
}
__global__ __launch_bounds__(256) void conv_w(const float4* __restrict__ qw,
                                              const float4* __restrict__ kw) {
    size_t i = (size_t)blockIdx.x * 256 + threadIdx.x;   // DDIM*EDIM/4
    const float4* W = blockIdx.y ? kw : qw;
    __half* oh = blockIdx.y ? g_wkh : g_wqh;
    __half* ol = blockIdx.y ? g_wkl : g_wql;
    float4 v = W[i];
    __half h[4], l[4];
    split2(v.x * 256.0f, h[0], l[0]); split2(v.y * 256.0f, h[1], l[1]);
    split2(v.z * 256.0f, h[2], l[2]); split2(v.w * 256.0f, h[3], l[3]);
    ((uint2*)oh)[i] = *(uint2*)h;
    ((uint2*)ol)[i] = *(uint2*)l;
}

// ---------------- proj: grid (4, 256, 2) ----------------
__global__ __launch_bounds__(256, 2) void proj_kernel()
{
    extern __shared__ __align__(16) char dsm[];
    const int tid = threadIdx.x, lane = tid & 31, wid = tid >> 5;
    const int warpM = wid >> 1, warpN = wid & 1;
    const int mBase = blockIdx.y * 128, nBase = blockIdx.x * 64;
    const __half* Ah = g_xh + (size_t)mBase * DDIM;           // [m][k]
    const __half* Al = g_xl + (size_t)mBase * DDIM;
    const __half* Bh = (blockIdx.z ? g_wkh : g_wqh) + nBase;  // [k][n]
    const __half* Bl = (blockIdx.z ? g_wkl : g_wql) + nBase;
    __half* Oh = blockIdx.z ? g_kh : g_qh;
    __half* Ol = blockIdx.z ? g_kl : g_ql;

    // A: 128 rows x 32 halves = 512 x 8-half chunks, 2 per thread
    const int am0 = tid >> 2, ac0 = (tid & 3) * 8;
    const int am1 = (tid + 256) >> 2, ac1 = ((tid + 256) & 3) * 8;
    // B: 32 rows x 64 halves = 256 chunks, 1 per thread
    const int bk = tid >> 3, bn = (tid & 7) * 8;
    const uint32_t sbase = sptr(dsm);
    const uint32_t dA0a = sbase + (am0 * SPA + ac0) * 2;
    const uint32_t dA0b = sbase + (am1 * SPA + ac1) * 2;
    const uint32_t dB0  = sbase + SBOFF + (bk * SPB + bn) * 2;

    ACC_DECL;
    const int NK = DDIM / 32;
#define PROJ_CP(s, k0)                                                         \
    do {                                                                       \
        CP16(dA0a + (s) * ASTAGE,          Ah + (size_t)am0 * DDIM + (k0) + ac0); \
        CP16(dA0a + (s) * ASTAGE + A_HL,   Al + (size_t)am0 * DDIM + (k0) + ac0); \
        CP16(dA0b + (s) * ASTAGE,          Ah + (size_t)am1 * DDIM + (k0) + ac1); \
        CP16(dA0b + (s) * ASTAGE + A_HL,   Al + (size_t)am1 * DDIM + (k0) + ac1); \
        CP16(dB0 + (s) * BSTAGE,           Bh + (size_t)((k0) + bk) * EDIM + bn); \
        CP16(dB0 + (s) * BSTAGE + B_HL,    Bl + (size_t)((k0) + bk) * EDIM + bn); \
        CP_COMMIT();                                                           \
    } while (0)

    PROJ_CP(0, 0);
    for (int t = 0; t < NK; t++) {
        if (t + 1 < NK) { PROJ_CP((t + 1) & 1, (t + 1) * 32); CP_WAIT1(); }
        else            { CP_WAIT0(); }
        __syncthreads();
        int s = t & 1;
        mma_rowA32((const __half*)(dsm + s * ASTAGE),
                   (const __half*)(dsm + s * ASTAGE + A_HL),
                   (const __half*)(dsm + SBOFF + s * BSTAGE),
                   (const __half*)(dsm + SBOFF + s * BSTAGE + B_HL),
                   acc, warpM, warpN);
        __syncthreads();
    }
#undef PROJ_CP

    // epilogue: v = exp(acc/256)/16, split hi/lo, coalesced write
    float* stage = reinterpret_cast<float*>(dsm) + wid * 256;
    const float ie = 1.0f / 256.0f;
    const int r = lane >> 1, c0 = (lane & 1) * 8;
#pragma unroll
    for (int mi = 0; mi < 2; mi++)
#pragma unroll
        for (int nj = 0; nj < 2; nj++) {
            wmma::store_matrix_sync(stage, acc[mi][nj], 16, wmma::mem_row_major);
            __syncwarp();
            int rg = mBase + warpM * 32 + mi * 16 + r;
            int cg = nBase + warpN * 32 + nj * 16 + c0;
            __half hb[8], lb[8];
#pragma unroll
            for (int j = 0; j < 8; j++) {
                float v = expf(stage[r * 16 + c0 + j] * ie) * 0.0625f;
                split2(v, hb[j], lb[j]);
            }
            *(uint4*)(Oh + (size_t)rg * EDIM + cg) = *(uint4*)hb;
            *(uint4*)(Ol + (size_t)rg * EDIM + cg) = *(uint4*)lb;
            __syncwarp();
        }
}

// ---------------- zc: one warp per row ----------------
__global__ __launch_bounds__(256) void zc_kernel()
{
    int row = (int)((blockIdx.x * 256 + threadIdx.x) >> 5);
    int lane = threadIdx.x & 31;
    const __half2* ph = (const __half2*)(g_qh + (size_t)row * EDIM);
    const __half2* pl = (const __half2*)(g_ql + (size_t)row * EDIM);
    float s = 0.0f;
#pragma unroll
    for (int i = 0; i < 4; i++) {
        float2 h = __half22float2(ph[lane + 32 * i]);
        float2 l = __half22float2(pl[lane + 32 * i]);
        s += (h.x + h.y) + (l.x + l.y);
    }
#pragma unroll
    for (int o = 16; o; o >>= 1) s += __shfl_xor_sync(0xffffffffu, s, o);
    if (lane == 0) g_zc[row] = 4096.0f / (16.0f * s + 1e-8f);
}

// ---------------- kv: grid (16, 2, 8) ----------------
__global__ __launch_bounds__(256, 2) void kv_kernel()
{
    extern __shared__ __align__(16) char dsm[];
    const int tid = threadIdx.x, lane = tid & 31, wid = tid >> 5;
    const int warpM = wid >> 1, warpN = wid & 1;
    const int b = blockIdx.z;
    const int mBase = blockIdx.y * 128;   // e
    const int nBase = blockIdx.x * 64;    // d
    const __half* Ah = g_kh + (size_t)b * LSEQ * EDIM + mBase;  // [k=l][m=e]
    const __half* Al = g_kl + (size_t)b * LSEQ * EDIM + mBase;
    const __half* Bh = g_xh + (size_t)b * LSEQ * DDIM + nBase;  // [k=l][n=d]
    const __half* Bl = g_xl + (size_t)b * LSEQ * DDIM + nBase;

    // A: 32 rows x 128 halves = 512 chunks, 2 per thread
    const int ak0 = tid >> 4, an0 = (tid & 15) * 8;
    const int ak1 = (tid + 256) >> 4, an1 = ((tid + 256) & 15) * 8;
    const int bk = tid >> 3, bn = (tid & 7) * 8;
    const uint32_t sbase = sptr(dsm);
    const uint32_t dA0a = sbase + (ak0 * SPK + an0) * 2;
    const uint32_t dA0b = sbase + (ak1 * SPK + an1) * 2;
    const uint32_t dB0  = sbase + SBOFF_K + (bk * SPB + bn) * 2;

    ACC_DECL;
    const int NK = LSEQ / 32;
#define KV_CP(s, k0)                                                           \
    do {                                                                       \
        CP16(dA0a + (s) * AKSTAGE,         Ah + (size_t)((k0) + ak0) * EDIM + an0); \
        CP16(dA0a + (s) * AKSTAGE + AK_HL, Al + (size_t)((k0) + ak0) * EDIM + an0); \
        CP16(dA0b + (s) * AKSTAGE,         Ah + (size_t)((k0) + ak1) * EDIM + an1); \
        CP16(dA0b + (s) * AKSTAGE + AK_HL, Al + (size_t)((k0) + ak1) * EDIM + an1); \
        CP16(dB0 + (s) * BSTAGE,           Bh + (size_t)((k0) + bk) * DDIM + bn);   \
        CP16(dB0 + (s) * BSTAGE + B_HL,    Bl + (size_t)((k0) + bk) * DDIM + bn);   \
        CP_COMMIT();                                                           \
    } while (0)

    KV_CP(0, 0);
    for (int t = 0; t < NK; t++) {
        if (t + 1 < NK) { KV_CP((t + 1) & 1, (t + 1) * 32); CP_WAIT1(); }
        else            { CP_WAIT0(); }
        __syncthreads();
        int s = t & 1;
        mma_colA32((const __half*)(dsm + s * AKSTAGE),
                   (const __half*)(dsm + s * AKSTAGE + AK_HL),
                   (const __half*)(dsm + SBOFF_K + s * BSTAGE),
                   (const __half*)(dsm + SBOFF_K + s * BSTAGE + B_HL),
                   acc, warpM, warpN);
        __syncthreads();
    }
#undef KV_CP

    // epilogue: kvh/kvl = split(acc/16) = split(kv/256)
    float* stage = reinterpret_cast<float*>(dsm) + wid * 256;
    __half* Oh = g_kvh + (size_t)b * EDIM * DDIM;
    __half* Ol = g_kvl + (size_t)b * EDIM * DDIM;
    const int r = lane >> 1, c0 = (lane & 1) * 8;
#pragma unroll
    for (int mi = 0; mi < 2; mi++)
#pragma unroll
        for (int nj = 0; nj < 2; nj++) {
            wmma::store_matrix_sync(stage, acc[mi][nj], 16, wmma::mem_row_major);
            __syncwarp();
            int rg = mBase + warpM * 32 + mi * 16 + r;
            int cg = nBase + warpN * 32 + nj * 16 + c0;
            __half hb[8], lb[8];
#pragma unroll
            for (int j = 0; j < 8; j++)
                split2(stage[r * 16 + c0 + j] * 0.0625f, hb[j], lb[j]);
            *(uint4*)(Oh + (size_t)rg * DDIM + cg) = *(uint4*)hb;
            *(uint4*)(Ol + (size_t)rg * DDIM + cg) = *(uint4*)lb;
            __syncwarp();
        }
}

// ---------------- num: grid (16, 32, 8) ----------------
__global__ __launch_bounds__(256, 2) void num_kernel(float* __restrict__ out)
{
    extern __shared__ __align__(16) char dsm[];
    const int tid = threadIdx.x, lane = tid & 31, wid = tid >> 5;
    const int warpM = wid >> 1, warpN = wid & 1;
    const int b = blockIdx.z;
    const int mBase = blockIdx.y * 128;   // l
    const int nBase = blockIdx.x * 64;    // d
    const __half* Ah = g_qh + ((size_t)b * LSEQ + mBase) * EDIM;  // [m=l][k=e]
    const __half* Al = g_ql + ((size_t)b * LSEQ + mBase) * EDIM;
    const __half* Bh = g_kvh + (size_t)b * EDIM * DDIM + nBase;   // [k=e][n=d]
    const __half* Bl = g_kvl + (size_t)b * EDIM * DDIM + nBase;

    const int am0 = tid >> 2, ac0 = (tid & 3) * 8;
    const int am1 = (tid + 256) >> 2, ac1 = ((tid + 256) & 3) * 8;
    const int bk = tid >> 3, bn = (tid & 7) * 8;
    const uint32_t sbase = sptr(dsm);
    const uint32_t dA0a = sbase + (am0 * SPA + ac0) * 2;
    const uint32_t dA0b = sbase + (am1 * SPA + ac1) * 2;
    const uint32_t dB0  = sbase + SBOFF + (bk * SPB + bn) * 2;

    ACC_DECL;
    const int NK = EDIM / 32;
#define NUM_CP(s, k0)                                                          \
    do {                                                                       \
        CP16(dA0a + (s) * ASTAGE,          Ah + (size_t)am0 * EDIM + (k0) + ac0); \
        CP16(dA0a + (s) * ASTAGE + A_HL,   Al + (size_t)am0 * EDIM + (k0) + ac0); \
        CP16(dA0b + (s) * ASTAGE,          Ah + (size_t)am1 * EDIM + (k0) + ac1); \
        CP16(dA0b + (s) * ASTAGE + A_HL,   Al + (size_t)am1 * EDIM + (k0) + ac1); \
        CP16(dB0 + (s) * BSTAGE,           Bh + (size_t)((k0) + bk) * DDIM + bn); \
        CP16(dB0 + (s) * BSTAGE + B_HL,    Bl + (size_t)((k0) + bk) * DDIM + bn); \
        CP_COMMIT();                                                           \
    } while (0)

    NUM_CP(0, 0);
    for (int t = 0; t < NK; t++) {
        if (t + 1 < NK) { NUM_CP((t + 1) & 1, (t + 1) * 32); CP_WAIT1(); }
        else            { CP_WAIT0(); }
        __syncthreads();
        int s = t & 1;
        mma_rowA32((const __half*)(dsm + s * ASTAGE),
                   (const __half*)(dsm + s * ASTAGE + A_HL),
                   (const __half*)(dsm + SBOFF + s * BSTAGE),
                   (const __half*)(dsm + SBOFF + s * BSTAGE + B_HL),
                   acc, warpM, warpN);
        __syncthreads();
    }
#undef NUM_CP

    // epilogue: out = acc * zc[row]
    float* stage = reinterpret_cast<float*>(dsm) + wid * 256;
    float* O = out + (size_t)b * LSEQ * DDIM;
    const int r = lane >> 1, c0 = (lane & 1) * 8;
#pragma unroll
    for (int mi = 0; mi < 2; mi++)
#pragma unroll
        for (int nj = 0; nj < 2; nj++) {
            wmma::store_matrix_sync(stage, acc[mi][nj], 16, wmma::mem_row_major);
            __syncwarp();
            int rg = mBase + warpM * 32 + mi * 16 + r;
            int cg = nBase + warpN * 32 + nj * 16 + c0;
            float zc = g_zc[b * LSEQ + rg];
            float ob[8];
#pragma unroll
            for (int j = 0; j < 8; j++)
                ob[j] = stage[r * 16 + c0 + j] * zc;
            *(float4*)(O + (size_t)rg * DDIM + cg)     = *(float4*)&ob[0];
            *(float4*)(O + (size_t)rg * DDIM + cg + 4) = *(float4*)&ob[4];
            __syncwarp();
        }
}

// ---------------- launch ----------------
extern "C" void kernel_launch(void* const* d_in, const int* in_sizes, int n_in,
                              void* d_out, int out_size)
{
    const float* x  = (const float*)d_in[0];
    const float* qw = (const float*)d_in[1];
    const float* kw = (const float*)d_in[2];
    float* out = (float*)d_out;

    cudaFuncSetAttribute(proj_kernel, cudaFuncAttributeMaxDynamicSharedMemorySize, SMEM_PN);
    cudaFuncSetAttribute(kv_kernel,   cudaFuncAttributeMaxDynamicSharedMemorySize, SMEM_KV);
    cudaFuncSetAttribute(num_kernel,  cudaFuncAttributeMaxDynamicSharedMemorySize, SMEM_PN);

    conv_x<<<(int)((size_t)BL * DDIM / 4 / 256), 256>>>((const float4*)x);
    conv_w<<<dim3(DDIM * EDIM / 4 / 256, 2), 256>>>((const float4*)qw,
                                                    (const float4*)kw);
    proj_kernel<<<dim3(EDIM / 64, BL / 128, 2), 256, SMEM_PN>>>();
    zc_kernel<<<BL / 8, 256>>>();
    kv_kernel<<<dim3(DDIM / 64, EDIM / 128, BATCH), 256, SMEM_KV>>>();
    num_kernel<<<dim3(DDIM / 64, LSEQ / 128, BATCH), 256, SMEM_PN>>>(out);
}